// round 12
// baseline (speedup 1.0000x reference)
#include <cuda_runtime.h>
#include <cstdint>

// EquivariantLayerNorm: N=262144 rows, DIM = 128 (scalar LN w/ weight+bias)
//                       + 64*3 + 32*5 (segment norms) = 480 fp32.
// HBM-streaming bound (~1.0 GB). Converged facts:
//   - All-float4 STG path: ~84% DRAM-active (R1: 147.5us, R8: 146.0us).
//   - Scalar stride-3/5 STGs fragment write sectors and regress (R4: 73.7%).
// R11: test the bulk-store theory with the SAFEST shape — one block-level
// cp.async.bulk of the whole 30720B tile (240 contiguous sectors), issued by
// thread 0 after __syncthreads. Single commit + wait, no divergent per-warp
// async ops (R9's per-warp variant hit repeated container failures).

#define S_DIM 128
#define DIM 480
#define ROWS_PER_BLOCK 16
#define THREADS 512
#define EPS 1e-5f
#define TILE_BYTES (ROWS_PER_BLOCK * DIM * 4)

__global__ __launch_bounds__(THREADS) void eqln_kernel(
    const float* __restrict__ x,
    const float* __restrict__ weight,
    const float* __restrict__ bias,
    float* __restrict__ out)
{
    __shared__ __align__(128) float tile[ROWS_PER_BLOCK * DIM];   // 30720 B
    __shared__ float sw[S_DIM];
    __shared__ float sb[S_DIM];

    const int tid = threadIdx.x;
    if (tid < S_DIM) {
        sw[tid] = weight[tid];
        sb[tid] = bias[tid];
    }

    const long long base = (long long)blockIdx.x * (ROWS_PER_BLOCK * DIM);

    // ---- Coalesced vectorized gather of 16 rows into shared ----
    // 16 rows * 480 floats = 1920 float4
    const float4* __restrict__ src4 = reinterpret_cast<const float4*>(x + base);
    float4* t4 = reinterpret_cast<float4*>(tile);
    #pragma unroll
    for (int i = tid; i < ROWS_PER_BLOCK * DIM / 4; i += THREADS)
        t4[i] = __ldcs(src4 + i);
    __syncthreads();

    const int warp = tid >> 5;
    const int lane = tid & 31;
    float* row = tile + warp * DIM;

    // ---- Scalar LayerNorm over first 128 elements (1 warp per row) ----
    // Lane owns 4 CONTIGUOUS elements: one LDS.128 in, one STS.128 back.
    const float4 v = *reinterpret_cast<const float4*>(row + 4 * lane);
    float s  = v.x + v.y + v.z + v.w;
    float ss = v.x * v.x + v.y * v.y + v.z * v.z + v.w * v.w;
    #pragma unroll
    for (int o = 16; o > 0; o >>= 1) {
        s  += __shfl_xor_sync(0xFFFFFFFFu, s,  o);
        ss += __shfl_xor_sync(0xFFFFFFFFu, ss, o);
    }
    const float mean = s * (1.0f / 128.0f);
    const float var  = ss * (1.0f / 128.0f) - mean * mean;
    const float inv  = rsqrtf(var + EPS);

    const float4 w4 = *reinterpret_cast<const float4*>(sw + 4 * lane);
    const float4 b4 = *reinterpret_cast<const float4*>(sb + 4 * lane);
    float4 o;
    o.x = (v.x - mean) * inv * w4.x + b4.x;
    o.y = (v.y - mean) * inv * w4.y + b4.y;
    o.z = (v.z - mean) * inv * w4.z + b4.z;
    o.w = (v.w - mean) * inv * w4.w + b4.w;
    *reinterpret_cast<float4*>(row + 4 * lane) = o;

    // ---- Segment norms: 64 groups of d=3 (offset 128) + 32 groups of d=5 (offset 320) ----
    // Per-lane: 2 groups of d=3, 1 group of d=5. gcd(3,32)=gcd(5,32)=1 ->
    // conflict-free scalar smem access. Results written back IN PLACE in smem.
    #pragma unroll
    for (int gi = 0; gi < 2; gi++) {
        const int g = lane + gi * 32;                  // 0..63
        float* p = row + S_DIM + 3 * g;
        float a = p[0], b = p[1], c = p[2];
        float m = (a + b + c) * (1.0f / 3.0f);
        float da = a - m, db = b - m, dc = c - m;
        float vr = (da * da + db * db + dc * dc) * (1.0f / 3.0f);
        float iv = rsqrtf(vr + EPS);
        p[0] = da * iv;
        p[1] = db * iv;
        p[2] = dc * iv;
    }
    {
        float* p = row + S_DIM + 64 * 3 + 5 * lane;
        float a = p[0], b = p[1], c = p[2], d = p[3], e = p[4];
        float m = (a + b + c + d + e) * 0.2f;
        float da = a - m, db = b - m, dc = c - m, dd = d - m, de = e - m;
        float vr = (da * da + db * db + dc * dc + dd * dd + de * de) * 0.2f;
        float iv = rsqrtf(vr + EPS);
        p[0] = da * iv;
        p[1] = db * iv;
        p[2] = dc * iv;
        p[3] = dd * iv;
        p[4] = de * iv;
    }

    // ---- Block-level bulk store: whole tile (30720 B, 240 contiguous sectors) ----
    __syncthreads();
    if (tid == 0) {
        asm volatile("fence.proxy.async.shared::cta;" ::: "memory");
        uint32_t saddr = (uint32_t)__cvta_generic_to_shared(tile);
        asm volatile(
            "cp.async.bulk.global.shared::cta.bulk_group [%0], [%1], %2;"
            :: "l"(out + base), "r"(saddr), "n"(TILE_BYTES) : "memory");
        asm volatile("cp.async.bulk.commit_group;" ::: "memory");
        asm volatile("cp.async.bulk.wait_group.read 0;" ::: "memory");
    }
}

extern "C" void kernel_launch(void* const* d_in, const int* in_sizes, int n_in,
                              void* d_out, int out_size)
{
    const float* x      = (const float*)d_in[0];
    const float* weight = (const float*)d_in[1];
    const float* bias   = (const float*)d_in[2];
    float* out = (float*)d_out;

    const int n_rows = in_sizes[0] / DIM;            // 262144
    const int grid = n_rows / ROWS_PER_BLOCK;        // 16384

    eqln_kernel<<<grid, THREADS>>>(x, weight, bias, out);
}

// round 17
// speedup vs baseline: 1.0213x; 1.0213x over previous
#include <cuda_runtime.h>

// EquivariantLayerNorm: N=262144 rows, DIM = 128 (scalar LN w/ weight+bias)
//                       + 64*3 + 32*5 (segment norms) = 480 fp32.
// HBM-streaming bound (~1.0 GB). Converged facts:
//   - DRAM-active pinned at ~84% across smem->STG (R1), direct STG (R8),
//     and cp.async.bulk (R11) store paths -> request shape at LTS is not
//     the binder; suspect R/W phase alignment from block barriers.
//   - Scalar stride-3/5 STGs fragment write sectors and regress (R4).
// R13 == R12 re-bench (R12 hit the recurring infra flake, never ran):
// fully warp-decoupled pipeline. Each warp owns its row end-to-end:
//   - LN's 32 float4 load straight to REGISTERS (lane <-> float4 idx lane
//     is exactly the LN layout) -- never touches smem.
//   - Tail (88 float4) staged in a per-warp smem slice solely for the
//     stride-3/5 regrouping; __syncwarp() only.
//   - ZERO block-wide barriers: warps slip freely -> smooth R/W interleave.
//   - All gmem writes remain full float4 __stcs.

#define S_DIM 128
#define DIM 480
#define TAIL 352                       // DIM - S_DIM floats
#define ROWS_PER_BLOCK 16
#define THREADS 512
#define EPS 1e-5f

__global__ __launch_bounds__(THREADS) void eqln_kernel(
    const float* __restrict__ x,
    const float* __restrict__ weight,
    const float* __restrict__ bias,
    float* __restrict__ out)
{
    __shared__ __align__(16) float stail[ROWS_PER_BLOCK * TAIL];   // 22528 B

    const int tid  = threadIdx.x;
    const int warp = tid >> 5;
    const int lane = tid & 31;

    const long long rbase = (long long)(blockIdx.x * ROWS_PER_BLOCK + warp) * DIM;
    const float4* __restrict__ in4  = reinterpret_cast<const float4*>(x + rbase);
    float4* __restrict__       out4 = reinterpret_cast<float4*>(out + rbase);

    float* srow = stail + warp * TAIL;
    float4* srow4 = reinterpret_cast<float4*>(srow);

    // ---- Per-warp gather: LN part to registers, tail to smem ----
    // float4 indices: [0,32) = LN (registers), [32,120) = tail (smem).
    const int l24 = (lane < 24) ? lane : 23;         // clamped idx for 3rd chunk
    const float4 v  = __ldcs(in4 + lane);            // LN: floats 4*lane..4*lane+3
    const float4 t0 = __ldcs(in4 + 32 + lane);
    const float4 t1 = __ldcs(in4 + 64 + lane);
    const float4 t2 = __ldcs(in4 + 96 + l24);

    srow4[lane]      = t0;
    srow4[lane + 32] = t1;
    if (lane < 24) srow4[lane + 64] = t2;

    // ---- Scalar LayerNorm over first 128 floats (register-resident) ----
    float s  = v.x + v.y + v.z + v.w;
    float ss = v.x * v.x + v.y * v.y + v.z * v.z + v.w * v.w;
    #pragma unroll
    for (int o = 16; o > 0; o >>= 1) {
        s  += __shfl_xor_sync(0xFFFFFFFFu, s,  o);
        ss += __shfl_xor_sync(0xFFFFFFFFu, ss, o);
    }
    const float mean = s * (1.0f / 128.0f);
    const float var  = ss * (1.0f / 128.0f) - mean * mean;
    const float inv  = rsqrtf(var + EPS);

    const float4 w4 = __ldg(reinterpret_cast<const float4*>(weight) + lane);
    const float4 b4 = __ldg(reinterpret_cast<const float4*>(bias) + lane);
    float4 o;
    o.x = (v.x - mean) * inv * w4.x + b4.x;
    o.y = (v.y - mean) * inv * w4.y + b4.y;
    o.z = (v.z - mean) * inv * w4.z + b4.z;
    o.w = (v.w - mean) * inv * w4.w + b4.w;
    __stcs(out4 + lane, o);                          // coalesced STG.128

    // ---- Segment norms on the smem tail ----
    // srow[i] == row float 128+i. 64 groups of d=3 (i in [0,192)),
    // 32 groups of d=5 (i in [192,352)). gcd(3,32)=gcd(5,32)=1 -> conflict-free.
    __syncwarp();
    #pragma unroll
    for (int gi = 0; gi < 2; gi++) {
        const int g = lane + gi * 32;                // 0..63
        float* p = srow + 3 * g;
        float a = p[0], b = p[1], c = p[2];
        float m = (a + b + c) * (1.0f / 3.0f);
        float da = a - m, db = b - m, dc = c - m;
        float vr = (da * da + db * db + dc * dc) * (1.0f / 3.0f);
        float iv = rsqrtf(vr + EPS);
        p[0] = da * iv;
        p[1] = db * iv;
        p[2] = dc * iv;
    }
    {
        float* p = srow + 192 + 5 * lane;
        float a = p[0], b = p[1], c = p[2], d = p[3], e = p[4];
        float m = (a + b + c + d + e) * 0.2f;
        float da = a - m, db = b - m, dc = c - m, dd = d - m, de = e - m;
        float vr = (da * da + db * db + dc * dc + dd * dd + de * de) * 0.2f;
        float iv = rsqrtf(vr + EPS);
        p[0] = da * iv;
        p[1] = db * iv;
        p[2] = dc * iv;
        p[3] = dd * iv;
        p[4] = de * iv;
    }

    // ---- Per-warp coalesced tail store: 88 float4 ----
    __syncwarp();
    const float4 c0 = srow4[lane];
    const float4 c1 = srow4[lane + 32];
    __stcs(out4 + 32 + lane, c0);
    __stcs(out4 + 64 + lane, c1);
    if (lane < 24) {
        const float4 c2 = srow4[lane + 64];
        __stcs(out4 + 96 + lane, c2);
    }
}

extern "C" void kernel_launch(void* const* d_in, const int* in_sizes, int n_in,
                              void* d_out, int out_size)
{
    const float* x      = (const float*)d_in[0];
    const float* weight = (const float*)d_in[1];
    const float* bias   = (const float*)d_in[2];
    float* out = (float*)d_out;

    const int n_rows = in_sizes[0] / DIM;            // 262144
    const int grid = n_rows / ROWS_PER_BLOCK;        // 16384

    eqln_kernel<<<grid, THREADS>>>(x, weight, bias, out);
}